// round 1
// baseline (speedup 1.0000x reference)
#include <cuda_runtime.h>

// PolynomialMoE: N=1048576 tokens, DIM=2, HID=64, E=4, hard top-1 routing.
// Output layout (float32): [ out (N*2) | router_logits (N*4) ]
//
// Strategy: fp32 packed-pair math via Blackwell fma.rn.f32x2 (FFMA2).
// All weights staged in SMEM with expert-stride padding (+8 floats) so the
// per-lane expert-dependent addresses hit distinct bank groups (broadcast,
// conflict-free). w2 is stored transposed so the K dimension is contiguous
// and the inner loop is LDS.128 + 2x FFMA2. Layer3 fused into layer2 epilogue.

typedef unsigned long long U64;

__device__ __forceinline__ U64 fma2(U64 a, U64 b, U64 c) {
    U64 d;
    asm("fma.rn.f32x2 %0, %1, %2, %3;" : "=l"(d) : "l"(a), "l"(b), "l"(c));
    return d;
}
__device__ __forceinline__ U64 pack2(float lo, float hi) {
    U64 r;
    asm("mov.b64 %0, {%1, %2};" : "=l"(r) : "f"(lo), "f"(hi));
    return r;
}
__device__ __forceinline__ void unpack2(U64 v, float& lo, float& hi) {
    asm("mov.b64 {%0, %1}, %2;" : "=f"(lo), "=f"(hi) : "l"(v));
}

// SMEM layout (floats), with padding so expert-dependent lane addresses are
// conflict-free (stride mod 32 gives bank offsets {0,8,16,24} across experts):
//   w2t : 4 experts * 4104  (64*64 transposed + 8 pad)          = 16416
//   w1s : 4 * 136           (2*64 + 8 pad)                      =   544
//   b1s : 4 * 72            (64 + 8 pad)                        =   288
//   b2s : 4 * 72                                                =   288
//   w3p : 4 * 68 u64 pairs  (64 pairs + 4 pad)  -> 544 floats
//   b3p : 4 u64 pairs                           ->   8 floats
//   rWs : 8 floats, rbs : 4 floats
static constexpr int W2T_STRIDE = 4104;
static constexpr int OFF_W1  = 16416;
static constexpr int OFF_B1  = OFF_W1 + 544;    // 16960
static constexpr int OFF_B2  = OFF_B1 + 288;    // 17248
static constexpr int OFF_W3  = OFF_B2 + 288;    // 17536 (u64-aligned: byte 70144)
static constexpr int OFF_B3  = OFF_W3 + 544;    // 18080
static constexpr int OFF_RW  = OFF_B3 + 8;      // 18088
static constexpr int OFF_RB  = OFF_RW + 8;      // 18096
static constexpr int SMEM_FLOATS = OFF_RB + 4;  // 18100
static constexpr int SMEM_BYTES  = SMEM_FLOATS * 4;  // 72400

static constexpr int THREADS = 256;
static constexpr int BLOCKS  = 456;

__global__ __launch_bounds__(THREADS, 2)
void moe_kernel(const float* __restrict__ x,
                const float* __restrict__ rW,
                const float* __restrict__ rb,
                const float* __restrict__ w1,
                const float* __restrict__ b1,
                const float* __restrict__ w2,
                const float* __restrict__ b2,
                const float* __restrict__ w3,
                const float* __restrict__ b3,
                float* __restrict__ out,
                int n_tok)
{
    extern __shared__ float smem[];
    float* w2t = smem;
    float* w1s = smem + OFF_W1;
    float* b1s = smem + OFF_B1;
    float* b2s = smem + OFF_B2;
    float* w3f = smem + OFF_W3;   // viewed as u64 pairs
    float* b3f = smem + OFF_B3;
    float* rWs = smem + OFF_RW;
    float* rbs = smem + OFF_RB;

    const int tid = threadIdx.x;

    // ---- stage weights into SMEM ----
    for (int t = tid; t < 4 * 64 * 64; t += THREADS) {
        int e = t >> 12, r = t & 4095, i = r >> 6, j = r & 63;
        w2t[e * W2T_STRIDE + j * 64 + i] = w2[t];   // transpose: [e][j][i]
    }
    for (int t = tid; t < 512; t += THREADS) {
        int e = t >> 7, r = t & 127;                // r = d*64 + i
        w1s[e * 136 + r] = w1[t];
    }
    for (int t = tid; t < 256; t += THREADS) {
        int e = t >> 6, i = t & 63;
        b1s[e * 72 + i] = b1[t];
        b2s[e * 72 + i] = b2[t];
    }
    for (int t = tid; t < 512; t += THREADS) {
        int e = t >> 7, r = t & 127, j = r >> 1, d = r & 1;   // w3[e][j][d]
        w3f[(e * 68 + j) * 2 + d] = w3[t];
    }
    if (tid < 8)  b3f[tid] = b3[tid];   // b3[e*2+d], contiguous pairs
    if (tid < 8)  rWs[tid] = rW[tid];
    if (tid < 4)  rbs[tid] = rb[tid];
    __syncthreads();

    const int stride = gridDim.x * blockDim.x;
    float* const logits_out = out + 2 * (size_t)n_tok;

    for (int n = blockIdx.x * blockDim.x + tid; n < n_tok; n += stride) {
        const float2 xv = ((const float2*)x)[n];
        const float x0 = xv.x, x1 = xv.y;

        // ---- router + argmax (first max, matching jnp.argmax) ----
        float l0 = fmaf(x0, rWs[0], fmaf(x1, rWs[4], rbs[0]));
        float l1 = fmaf(x0, rWs[1], fmaf(x1, rWs[5], rbs[1]));
        float l2 = fmaf(x0, rWs[2], fmaf(x1, rWs[6], rbs[2]));
        float l3 = fmaf(x0, rWs[3], fmaf(x1, rWs[7], rbs[3]));
        int best = 0; float bl = l0;
        if (l1 > bl) { bl = l1; best = 1; }
        if (l2 > bl) { bl = l2; best = 2; }
        if (l3 > bl) { bl = l3; best = 3; }
        ((float4*)logits_out)[n] = make_float4(l0, l1, l2, l3);

        // ---- layer 1: h1 = relu(x0*w1[:,0] + x1*w1[:,1] + b1), packed pairs ----
        const U64 x0x2 = pack2(x0, x0);
        const U64 x1x2 = pack2(x1, x1);
        const U64* a0 = (const U64*)(w1s + best * 136);        // d=0 pairs
        const U64* a1 = (const U64*)(w1s + best * 136 + 64);   // d=1 pairs
        const U64* cb = (const U64*)(b1s + best * 72);
        U64 hx[32];
        #pragma unroll
        for (int p = 0; p < 32; p++) {
            U64 u = fma2(x1x2, a1[p], cb[p]);
            u = fma2(x0x2, a0[p], u);
            float ulo, uhi; unpack2(u, ulo, uhi);
            hx[p] = pack2(fmaxf(ulo, 0.f), fmaxf(uhi, 0.f));
        }

        // ---- layer 2 + fused layer 3 ----
        const float* w2e = w2t + best * W2T_STRIDE;
        const float* b2e = b2s + best * 72;
        const U64*   w3e = (const U64*)w3f + best * 68;
        U64 oacc = ((const U64*)b3f)[best];   // init with b3 pair

        #pragma unroll 2
        for (int j = 0; j < 64; j++) {
            const ulonglong2* wr = (const ulonglong2*)(w2e + j * 64);
            U64 acc0 = 0ull, acc1 = 0ull;     // two packed zero floats each
            #pragma unroll
            for (int q = 0; q < 16; q++) {
                ulonglong2 w = wr[q];
                acc0 = fma2(hx[2 * q],     w.x, acc0);
                acc1 = fma2(hx[2 * q + 1], w.y, acc1);
            }
            float a, b, c, d;
            unpack2(acc0, a, b);
            unpack2(acc1, c, d);
            float h2 = (a + b) + (c + d) + b2e[j];
            h2 = fmaxf(h2, 0.f);
            oacc = fma2(pack2(h2, h2), w3e[j], oacc);   // out += h2 * w3[j][0:2]
        }
        ((U64*)out)[n] = oacc;   // out[2n], out[2n+1]
    }
}

extern "C" void kernel_launch(void* const* d_in, const int* in_sizes, int n_in,
                              void* d_out, int out_size)
{
    const float* x  = (const float*)d_in[0];
    const float* rW = (const float*)d_in[1];
    const float* rb = (const float*)d_in[2];
    const float* w1 = (const float*)d_in[3];
    const float* b1 = (const float*)d_in[4];
    const float* w2 = (const float*)d_in[5];
    const float* b2 = (const float*)d_in[6];
    const float* w3 = (const float*)d_in[7];
    const float* b3 = (const float*)d_in[8];
    float* out = (float*)d_out;

    const int n_tok = in_sizes[0] / 2;   // x is [N, 2]

    cudaFuncSetAttribute(moe_kernel,
                         cudaFuncAttributeMaxDynamicSharedMemorySize,
                         SMEM_BYTES);

    moe_kernel<<<BLOCKS, THREADS, SMEM_BYTES>>>(
        x, rW, rb, w1, b1, w2, b2, w3, b3, out, n_tok);
}

// round 3
// speedup vs baseline: 2.3093x; 2.3093x over previous
#include <cuda_runtime.h>

// PolynomialMoE: N=1048576, DIM=2, HID=64, E=4, hard top-1 routing.
// Output layout (float32): [ out (N*2) | router_logits (N*4) ]
//
// R3: identical to R2 except the expert-kernel grid covers the worst-case
// tile count N/TILE + (E-1): per-expert ceil() rounding can need up to 3
// extra tiles beyond N/TILE. R2's exact-4096 grid left up to 765 tokens
// unprocessed (0xAA poison) -> rel_err 7e-3.

typedef unsigned long long U64;

static constexpr int N_MAX = 1 << 20;
static constexpr int TILE  = 256;

__device__ int d_cnt[4];
__device__ int d_perm[4 * N_MAX];

__device__ __forceinline__ U64 fma2(U64 a, U64 b, U64 c) {
    U64 d;
    asm("fma.rn.f32x2 %0, %1, %2, %3;" : "=l"(d) : "l"(a), "l"(b), "l"(c));
    return d;
}
__device__ __forceinline__ U64 pack2(float lo, float hi) {
    U64 r;
    asm("mov.b64 %0, {%1, %2};" : "=l"(r) : "f"(lo), "f"(hi));
    return r;
}
__device__ __forceinline__ void unpack2(U64 v, float& lo, float& hi) {
    asm("mov.b64 {%0, %1}, %2;" : "=f"(lo), "=f"(hi) : "l"(v));
}

__global__ void zero_kernel() {
    if (threadIdx.x < 4) d_cnt[threadIdx.x] = 0;
}

// ---------------- Kernel 1: router + bucketing ----------------
__global__ __launch_bounds__(256)
void router_kernel(const float* __restrict__ x,
                   const float* __restrict__ rW,
                   const float* __restrict__ rb,
                   float* __restrict__ out,
                   int n)
{
    const int i = blockIdx.x * 256 + threadIdx.x;
    if (i >= n) return;

    const float2 xv = ((const float2*)x)[i];
    const float l0 = fmaf(xv.x, rW[0], fmaf(xv.y, rW[4], rb[0]));
    const float l1 = fmaf(xv.x, rW[1], fmaf(xv.y, rW[5], rb[1]));
    const float l2 = fmaf(xv.x, rW[2], fmaf(xv.y, rW[6], rb[2]));
    const float l3 = fmaf(xv.x, rW[3], fmaf(xv.y, rW[7], rb[3]));

    int best = 0; float bl = l0;
    if (l1 > bl) { bl = l1; best = 1; }
    if (l2 > bl) { bl = l2; best = 2; }
    if (l3 > bl) { bl = l3; best = 3; }

    ((float4*)(out + 2 * (size_t)n))[i] = make_float4(l0, l1, l2, l3);

    const unsigned lane = threadIdx.x & 31;
    unsigned m[4];
    #pragma unroll
    for (int e = 0; e < 4; e++)
        m[e] = __ballot_sync(0xffffffffu, best == e);

    const unsigned mym   = m[best];
    const int rank       = __popc(mym & ((1u << lane) - 1));
    const int leader     = __ffs(mym) - 1;

    int b_l = 0;
    if ((int)lane == leader)
        b_l = atomicAdd(&d_cnt[best], __popc(mym));
    const int base = __shfl_sync(0xffffffffu, b_l, leader);

    d_perm[best * N_MAX + base + rank] = i;
}

// ---------------- Kernel 2: grouped expert MLP ----------------
static constexpr int OFF_H1T = 4096;
static constexpr int OFF_W1  = OFF_H1T + 64 * TILE;  // 20480
static constexpr int OFF_B1  = OFF_W1 + 128;         // 20608
static constexpr int OFF_B2  = OFF_B1 + 64;          // 20672
static constexpr int OFF_W3  = OFF_B2 + 64;          // 20736 (8B aligned)
static constexpr int OFF_B3  = OFF_W3 + 128;         // 20864
static constexpr int OFF_IDX = OFF_B3 + 4;           // 20868
static constexpr int SMEM_FLOATS = OFF_IDX + 256;    // 21124
static constexpr int SMEM_BYTES  = SMEM_FLOATS * 4;  // 84496

__global__ __launch_bounds__(256, 2)
void expert_kernel(const float* __restrict__ x,
                   const float* __restrict__ w1,
                   const float* __restrict__ b1,
                   const float* __restrict__ w2,
                   const float* __restrict__ b2,
                   const float* __restrict__ w3,
                   const float* __restrict__ b3,
                   float* __restrict__ out)
{
    extern __shared__ float sm[];
    float* w2s = sm;
    float* h1T = sm + OFF_H1T;
    float* w1s = sm + OFF_W1;
    float* b1s = sm + OFF_B1;
    float* b2s = sm + OFF_B2;
    float* w3f = sm + OFF_W3;
    float* b3f = sm + OFF_B3;
    int*   idxs = (int*)(sm + OFF_IDX);

    // Map blockIdx.x -> (expert, local tile)
    const int c0 = d_cnt[0], c1 = d_cnt[1], c2 = d_cnt[2], c3 = d_cnt[3];
    const int t0 = (c0 + TILE - 1) / TILE;
    const int t1 = (c1 + TILE - 1) / TILE;
    const int t2 = (c2 + TILE - 1) / TILE;
    const int t3 = (c3 + TILE - 1) / TILE;

    int b = blockIdx.x;
    int e, lo, cnt;
    if (b < t0)              { e = 0; lo = b; cnt = c0; }
    else if ((b -= t0) < t1) { e = 1; lo = b; cnt = c1; }
    else if ((b -= t1) < t2) { e = 2; lo = b; cnt = c2; }
    else if ((b -= t2) < t3) { e = 3; lo = b; cnt = c3; }
    else return;

    const int tid = threadIdx.x;

    // Stage this expert's weights
    {
        const float4* w2g = (const float4*)(w2 + e * 4096);
        #pragma unroll
        for (int t = tid; t < 1024; t += 256)
            ((float4*)w2s)[t] = w2g[t];
        if (tid < 128) w1s[tid] = w1[e * 128 + tid];
        if (tid < 64)  { b1s[tid] = b1[e * 64 + tid]; b2s[tid] = b2[e * 64 + tid]; }
        if (tid >= 128 && tid < 256) w3f[tid - 128] = w3[e * 128 + (tid - 128)];
        if (tid == 0) { b3f[0] = b3[e * 2]; b3f[1] = b3[e * 2 + 1]; }
    }

    const int tstart = lo * TILE;
    int m = cnt - tstart;
    if (m > TILE) m = TILE;

    const int token = d_perm[e * N_MAX + tstart + (tid < m ? tid : 0)];
    idxs[tid] = token;
    const float2 xv = ((const float2*)x)[token];

    __syncthreads();

    // Layer 1 into transposed SMEM: h1T[k][tid]
    #pragma unroll
    for (int i = 0; i < 64; i++) {
        float h = fmaf(xv.x, w1s[i], fmaf(xv.y, w1s[64 + i], b1s[i]));
        h1T[i * TILE + tid] = fmaxf(h, 0.f);
    }
    __syncthreads();

    // Layer 2 GEMM: 8 tokens x 8 j per thread, j packed in pairs (FFMA2)
    const int warp = tid >> 5, lane = tid & 31;
    const int tg = lane >> 3, jg = lane & 7;
    const int tb = warp * 32 + tg * 8;
    const int jb = jg * 8;

    const float* hP = h1T + tb;
    const float* wP = w2s + jb;

    U64 acc[8][4];
    {
        U64 b01 = pack2(b2s[jb + 0], b2s[jb + 1]);
        U64 b23 = pack2(b2s[jb + 2], b2s[jb + 3]);
        U64 b45 = pack2(b2s[jb + 4], b2s[jb + 5]);
        U64 b67 = pack2(b2s[jb + 6], b2s[jb + 7]);
        #pragma unroll
        for (int t = 0; t < 8; t++) {
            acc[t][0] = b01; acc[t][1] = b23; acc[t][2] = b45; acc[t][3] = b67;
        }
    }

    #pragma unroll 2
    for (int k = 0; k < 64; k++) {
        const float4 ha = *(const float4*)(hP + k * TILE);
        const float4 hb = *(const float4*)(hP + k * TILE + 4);
        const ulonglong2 wa = *(const ulonglong2*)(wP + k * 64);
        const ulonglong2 wb = *(const ulonglong2*)(wP + k * 64 + 4);
        const float hv[8] = { ha.x, ha.y, ha.z, ha.w, hb.x, hb.y, hb.z, hb.w };
        #pragma unroll
        for (int t = 0; t < 8; t++) {
            const U64 hh = pack2(hv[t], hv[t]);
            acc[t][0] = fma2(hh, wa.x, acc[t][0]);
            acc[t][1] = fma2(hh, wa.y, acc[t][1]);
            acc[t][2] = fma2(hh, wb.x, acc[t][2]);
            acc[t][3] = fma2(hh, wb.y, acc[t][3]);
        }
    }

    // Epilogue: relu + fused layer 3 partials over this thread's 8 j's
    const U64* w3e = (const U64*)w3f;
    U64 po[8];
    #pragma unroll
    for (int t = 0; t < 8; t++) {
        U64 o = 0ull;
        #pragma unroll
        for (int p = 0; p < 4; p++) {
            float a, c; unpack2(acc[t][p], a, c);
            a = fmaxf(a, 0.f); c = fmaxf(c, 0.f);
            o = fma2(pack2(a, a), w3e[jb + 2 * p],     o);
            o = fma2(pack2(c, c), w3e[jb + 2 * p + 1], o);
        }
        po[t] = o;
    }

    // Deterministic reduction across the 8 j-lanes (xor 1,2,4 stays in tg)
    #pragma unroll
    for (int t = 0; t < 8; t++) {
        float a, c; unpack2(po[t], a, c);
        #pragma unroll
        for (int s = 1; s < 8; s <<= 1) {
            a += __shfl_xor_sync(0xffffffffu, a, s);
            c += __shfl_xor_sync(0xffffffffu, c, s);
        }
        po[t] = pack2(a, c);
    }

    if (jg == 0) {
        const float b3a = b3f[0], b3c = b3f[1];
        #pragma unroll
        for (int t = 0; t < 8; t++) {
            const int ti = tb + t;
            if (ti < m) {
                float a, c; unpack2(po[t], a, c);
                ((float2*)out)[idxs[ti]] = make_float2(a + b3a, c + b3c);
            }
        }
    }
}

extern "C" void kernel_launch(void* const* d_in, const int* in_sizes, int n_in,
                              void* d_out, int out_size)
{
    const float* x  = (const float*)d_in[0];
    const float* rW = (const float*)d_in[1];
    const float* rb = (const float*)d_in[2];
    const float* w1 = (const float*)d_in[3];
    const float* b1 = (const float*)d_in[4];
    const float* w2 = (const float*)d_in[5];
    const float* b2 = (const float*)d_in[6];
    const float* w3 = (const float*)d_in[7];
    const float* b3 = (const float*)d_in[8];
    float* out = (float*)d_out;

    const int n_tok = in_sizes[0] / 2;

    cudaFuncSetAttribute(expert_kernel,
                         cudaFuncAttributeMaxDynamicSharedMemorySize,
                         SMEM_BYTES);

    zero_kernel<<<1, 32>>>();
    router_kernel<<<(n_tok + 255) / 256, 256>>>(x, rW, rb, out, n_tok);

    // Worst case: each expert's count rounds up -> N/TILE + (E-1) tiles.
    const int max_tiles = n_tok / TILE + 3;
    expert_kernel<<<max_tiles, 256, SMEM_BYTES>>>(x, w1, b1, w2, b2, w3, b3, out);
}

// round 5
// speedup vs baseline: 5.8911x; 2.5511x over previous
#include <cuda_runtime.h>
#include <cuda_bf16.h>
#include <cstdint>

// PolynomialMoE: N=1048576, DIM=2, HID=64, E=4, hard top-1.
// Output (float32): [ out (N*2) | router_logits (N*4) ]
//
// R5: tcgen05 unavailable (harness targets plain sm_103). Use baseline-PTX
// warp-level HMMA instead: mma.sync.m16n8k16 bf16 with 2-way bf16 split
// (A0B0 + A0B1 + A1B0; dropped A1B1 ~ 2^-18) and fp32 accumulators.
//  - router: block-aggregated bucketing (4 global atomics per CTA)
//  - prep: w2 -> 2 bf16 splits stored in per-thread MMA B-fragment order
//  - expert: 128 tokens/CTA, 4 warps; layer-1 h computed straight into
//    A fragments in registers (no SMEM roundtrip); epilogue fuses b2+relu+
//    layer3 with shfl reduction over the 4 lanes sharing a row.

typedef unsigned long long U64;

static constexpr int N_MAX = 1 << 20;
static constexpr int TILE  = 128;

__device__ int d_cnt[4];
__device__ int d_perm[4 * N_MAX];
// B fragments: [e][s][kt][nt][lane] uint2 (4 bf16 each) = 4*2*4*8*32
__device__ uint2 d_w2f[4 * 2 * 4 * 8 * 32];

// ---------------- helpers ----------------
__device__ __forceinline__ U64 fma2(U64 a, U64 b, U64 c) {
    U64 d;
    asm("fma.rn.f32x2 %0, %1, %2, %3;" : "=l"(d) : "l"(a), "l"(b), "l"(c));
    return d;
}
__device__ __forceinline__ U64 pack2(float lo, float hi) {
    U64 r;
    asm("mov.b64 %0, {%1, %2};" : "=l"(r) : "f"(lo), "f"(hi));
    return r;
}
__device__ __forceinline__ void unpack2(U64 v, float& lo, float& hi) {
    asm("mov.b64 {%0, %1}, %2;" : "=f"(lo), "=f"(hi) : "l"(v));
}
// pack two bf16 with guaranteed lo/hi ordering (lo = first arg)
__device__ __forceinline__ uint32_t packbf(__nv_bfloat16 lo, __nv_bfloat16 hi) {
    __nv_bfloat162 t = __halves2bfloat162(lo, hi);
    uint32_t r;
    memcpy(&r, &t, 4);
    return r;
}
// split v into bf16 main + bf16 residual
__device__ __forceinline__ void bsplit(float v, __nv_bfloat16& m, __nv_bfloat16& r) {
    m = __float2bfloat16(v);
    r = __float2bfloat16(v - __bfloat162float(m));
}

__device__ __forceinline__ void mma16816(float c[4], const uint32_t a[4],
                                         uint32_t b0, uint32_t b1) {
    asm volatile(
        "mma.sync.aligned.m16n8k16.row.col.f32.bf16.bf16.f32 "
        "{%0,%1,%2,%3}, {%4,%5,%6,%7}, {%8,%9}, {%0,%1,%2,%3};"
        : "+f"(c[0]), "+f"(c[1]), "+f"(c[2]), "+f"(c[3])
        : "r"(a[0]), "r"(a[1]), "r"(a[2]), "r"(a[3]), "r"(b0), "r"(b1));
}

// ---------------- Kernel 1: router + block-aggregated bucketing ----------
__global__ __launch_bounds__(256)
void router_kernel(const float* __restrict__ x,
                   const float* __restrict__ rW,
                   const float* __restrict__ rb,
                   float* __restrict__ out, int n)
{
    __shared__ int scnt[4], gbase[4];
    const int tid = threadIdx.x;
    if (tid < 4) scnt[tid] = 0;
    __syncthreads();

    const int i = blockIdx.x * 256 + tid;
    const float2 xv = ((const float2*)x)[i];
    const float l0 = fmaf(xv.x, rW[0], fmaf(xv.y, rW[4], rb[0]));
    const float l1 = fmaf(xv.x, rW[1], fmaf(xv.y, rW[5], rb[1]));
    const float l2 = fmaf(xv.x, rW[2], fmaf(xv.y, rW[6], rb[2]));
    const float l3 = fmaf(xv.x, rW[3], fmaf(xv.y, rW[7], rb[3]));
    int best = 0; float bl = l0;
    if (l1 > bl) { bl = l1; best = 1; }
    if (l2 > bl) { bl = l2; best = 2; }
    if (l3 > bl) { bl = l3; best = 3; }
    ((float4*)(out + 2 * (size_t)n))[i] = make_float4(l0, l1, l2, l3);

    const unsigned lane = tid & 31;
    unsigned m[4];
    #pragma unroll
    for (int e = 0; e < 4; e++) m[e] = __ballot_sync(0xffffffffu, best == e);
    const unsigned mym = m[best];
    const int rank   = __popc(mym & ((1u << lane) - 1));
    const int leader = __ffs(mym) - 1;

    int wb = 0;
    if ((int)lane == leader) wb = atomicAdd(&scnt[best], __popc(mym));
    wb = __shfl_sync(0xffffffffu, wb, leader);
    __syncthreads();
    if (tid < 4) gbase[tid] = atomicAdd(&d_cnt[tid], scnt[tid]);
    __syncthreads();

    d_perm[best * N_MAX + gbase[best] + wb + rank] = i;
}

// ---------------- Kernel 2: w2 -> bf16-split B fragments ------------------
// B[k][n] = w2[e][k][n].  Fragment element map (m16n8k16, col-major B):
//   thread lane holds (k0,k0+1) and (k0+8,k0+9) at n = nt*8 + lane/4,
//   k0 = kt*16 + (lane%4)*2.
__global__ __launch_bounds__(256)
void prep_kernel(const float* __restrict__ w2)
{
    const int e = blockIdx.x;
    for (int t = threadIdx.x; t < 1024; t += 256) {
        const int kt = t >> 8, nt = (t >> 5) & 7, lane = t & 31;
        const int k0 = kt * 16 + (lane & 3) * 2;
        const int n  = nt * 8 + (lane >> 2);
        const float v0 = w2[e * 4096 + k0 * 64 + n];
        const float v1 = w2[e * 4096 + (k0 + 1) * 64 + n];
        const float v2 = w2[e * 4096 + (k0 + 8) * 64 + n];
        const float v3 = w2[e * 4096 + (k0 + 9) * 64 + n];
        __nv_bfloat16 m0, r0, m1, r1, m2, r2, m3, r3;
        bsplit(v0, m0, r0); bsplit(v1, m1, r1);
        bsplit(v2, m2, r2); bsplit(v3, m3, r3);
        const int i0 = (((e * 2 + 0) * 4 + kt) * 8 + nt) * 32 + lane;
        const int i1 = (((e * 2 + 1) * 4 + kt) * 8 + nt) * 32 + lane;
        d_w2f[i0] = make_uint2(packbf(m0, m1), packbf(m2, m3));
        d_w2f[i1] = make_uint2(packbf(r0, r1), packbf(r2, r3));
    }
}

// ---------------- Kernel 3: expert tile (HMMA) ----------------------------
__global__ __launch_bounds__(128, 3)
void expert_kernel(const float* __restrict__ x,
                   const float* __restrict__ w1,
                   const float* __restrict__ b1,
                   const float* __restrict__ b2,
                   const float* __restrict__ w3,
                   const float* __restrict__ b3,
                   float* __restrict__ out)
{
    __shared__ uint2  sBf[2048];          // [s][kt][nt][lane]
    __shared__ float2 sX[128];
    __shared__ float  sW1[128];           // [d][i]
    __shared__ float  sB1[64], sB2[64];
    __shared__ __align__(8) float sW3[128];  // u64 pairs per j
    __shared__ float  sB3[2];
    __shared__ int    sIdx[128];

    // --- map blockIdx -> (expert, tile) ---
    const int c0 = d_cnt[0], c1 = d_cnt[1], c2 = d_cnt[2], c3 = d_cnt[3];
    const int t0 = (c0 + TILE - 1) / TILE, t1 = (c1 + TILE - 1) / TILE;
    const int t2 = (c2 + TILE - 1) / TILE, t3 = (c3 + TILE - 1) / TILE;
    int b = blockIdx.x, e, lo, cnt;
    if (b < t0)              { e = 0; lo = b; cnt = c0; }
    else if ((b -= t0) < t1) { e = 1; lo = b; cnt = c1; }
    else if ((b -= t1) < t2) { e = 2; lo = b; cnt = c2; }
    else if ((b -= t2) < t3) { e = 3; lo = b; cnt = c3; }
    else return;

    const int tid = threadIdx.x;
    const int tstart = lo * TILE;
    int mvalid = cnt - tstart;
    if (mvalid > TILE) mvalid = TILE;

    // --- stage ---
    {
        const uint4* gB = ((const uint4*)d_w2f) + e * 1024;
        uint4* sB4 = (uint4*)sBf;
        #pragma unroll
        for (int t = tid; t < 1024; t += 128) sB4[t] = gB[t];
        sW1[tid] = w1[e * 128 + tid];
        sW3[tid] = w3[e * 128 + tid];
        if (tid < 64) { sB1[tid] = b1[e * 64 + tid]; sB2[tid] = b2[e * 64 + tid]; }
        if (tid < 2)  sB3[tid] = b3[e * 2 + tid];
        const int token = d_perm[e * N_MAX + tstart + (tid < mvalid ? tid : 0)];
        sIdx[tid] = token;
        sX[tid] = ((const float2*)x)[token];
    }
    __syncthreads();

    const int lane = tid & 31, wid = tid >> 5;
    const int qr = lane >> 2;             // lane/4
    const int kb = (lane & 3) * 2;
    const int rbase = wid * 32 + qr;

    float xr[4], yr[4];
    #pragma unroll
    for (int r = 0; r < 4; r++) {         // rows rbase + {0,8,16,24}
        const float2 v = sX[rbase + r * 8];
        xr[r] = v.x; yr[r] = v.y;
    }

    float acc[2][8][4];
    #pragma unroll
    for (int mt = 0; mt < 2; mt++)
        #pragma unroll
        for (int nt = 0; nt < 8; nt++)
            #pragma unroll
            for (int q = 0; q < 4; q++) acc[mt][nt][q] = 0.f;

    #pragma unroll
    for (int kt = 0; kt < 4; kt++) {
        const int ks = kt * 16 + kb;
        const float wa0 = sW1[ks],      wa1 = sW1[ks + 1];
        const float wa8 = sW1[ks + 8],  wa9 = sW1[ks + 9];
        const float wb0 = sW1[64 + ks],     wb1 = sW1[64 + ks + 1];
        const float wb8 = sW1[64 + ks + 8], wb9 = sW1[64 + ks + 9];
        const float bb0 = sB1[ks],      bb1 = sB1[ks + 1];
        const float bb8 = sB1[ks + 8],  bb9 = sB1[ks + 9];

        uint32_t A0[2][4], A1[2][4];
        #pragma unroll
        for (int r = 0; r < 4; r++) {     // r = 2*mt + p (p = row pos 0/+8)
            const float h0 = fmaxf(fmaf(xr[r], wa0, fmaf(yr[r], wb0, bb0)), 0.f);
            const float h1 = fmaxf(fmaf(xr[r], wa1, fmaf(yr[r], wb1, bb1)), 0.f);
            const float h8 = fmaxf(fmaf(xr[r], wa8, fmaf(yr[r], wb8, bb8)), 0.f);
            const float h9 = fmaxf(fmaf(xr[r], wa9, fmaf(yr[r], wb9, bb9)), 0.f);
            __nv_bfloat16 m0, r0, m1, r1, m8, r8, m9, r9;
            bsplit(h0, m0, r0); bsplit(h1, m1, r1);
            bsplit(h8, m8, r8); bsplit(h9, m9, r9);
            const int mt = r >> 1, p = r & 1;
            A0[mt][p]     = packbf(m0, m1);
            A0[mt][p + 2] = packbf(m8, m9);
            A1[mt][p]     = packbf(r0, r1);
            A1[mt][p + 2] = packbf(r8, r9);
        }

        #pragma unroll
        for (int nt = 0; nt < 8; nt++) {
            const uint2 B0 = sBf[((0 * 4 + kt) * 8 + nt) * 32 + lane];
            const uint2 B1 = sBf[((1 * 4 + kt) * 8 + nt) * 32 + lane];
            #pragma unroll
            for (int mt = 0; mt < 2; mt++) {
                mma16816(acc[mt][nt], A0[mt], B0.x, B0.y);
                mma16816(acc[mt][nt], A0[mt], B1.x, B1.y);
                mma16816(acc[mt][nt], A1[mt], B0.x, B0.y);
            }
        }
    }

    // --- epilogue: b2 + relu + fused layer 3, reduce over 4 n-lanes ---
    const U64* w3p = (const U64*)sW3;
    #pragma unroll
    for (int mt = 0; mt < 2; mt++) {
        U64 po0 = 0ull, po1 = 0ull;
        #pragma unroll
        for (int nt = 0; nt < 8; nt++) {
            const int j0 = nt * 8 + kb, j1 = j0 + 1;
            float c;
            c = fmaxf(acc[mt][nt][0] + sB2[j0], 0.f);
            po0 = fma2(pack2(c, c), w3p[j0], po0);
            c = fmaxf(acc[mt][nt][1] + sB2[j1], 0.f);
            po0 = fma2(pack2(c, c), w3p[j1], po0);
            c = fmaxf(acc[mt][nt][2] + sB2[j0], 0.f);
            po1 = fma2(pack2(c, c), w3p[j0], po1);
            c = fmaxf(acc[mt][nt][3] + sB2[j1], 0.f);
            po1 = fma2(pack2(c, c), w3p[j1], po1);
        }
        float a0, a1, c0v, c1v;
        unpack2(po0, a0, a1);
        unpack2(po1, c0v, c1v);
        #pragma unroll
        for (int s = 1; s < 4; s <<= 1) {
            a0  += __shfl_xor_sync(0xffffffffu, a0,  s);
            a1  += __shfl_xor_sync(0xffffffffu, a1,  s);
            c0v += __shfl_xor_sync(0xffffffffu, c0v, s);
            c1v += __shfl_xor_sync(0xffffffffu, c1v, s);
        }
        if ((lane & 3) == 0) {
            const int r0 = wid * 32 + mt * 16 + qr;
            if (r0 < mvalid)
                ((float2*)out)[sIdx[r0]] =
                    make_float2(a0 + sB3[0], a1 + sB3[1]);
            const int r1 = r0 + 8;
            if (r1 < mvalid)
                ((float2*)out)[sIdx[r1]] =
                    make_float2(c0v + sB3[0], c1v + sB3[1]);
        }
    }
}

extern "C" void kernel_launch(void* const* d_in, const int* in_sizes, int n_in,
                              void* d_out, int out_size)
{
    const float* x  = (const float*)d_in[0];
    const float* rW = (const float*)d_in[1];
    const float* rb = (const float*)d_in[2];
    const float* w1 = (const float*)d_in[3];
    const float* b1 = (const float*)d_in[4];
    const float* w2 = (const float*)d_in[5];
    const float* b2 = (const float*)d_in[6];
    const float* w3 = (const float*)d_in[7];
    const float* b3 = (const float*)d_in[8];
    float* out = (float*)d_out;

    const int n_tok = in_sizes[0] / 2;

    void* cnt_addr = nullptr;
    cudaGetSymbolAddress(&cnt_addr, d_cnt);
    cudaMemsetAsync(cnt_addr, 0, 4 * sizeof(int));

    router_kernel<<<n_tok / 256, 256>>>(x, rW, rb, out, n_tok);
    prep_kernel<<<4, 256>>>(w2);

    const int max_tiles = n_tok / TILE + 3;   // per-expert ceil slack
    expert_kernel<<<max_tiles, 128>>>(x, w1, b1, b2, w3, b3, out);
}

// round 6
// speedup vs baseline: 7.4379x; 1.2626x over previous
#include <cuda_runtime.h>
#include <cuda_bf16.h>
#include <cstdint>

// PolynomialMoE: N=1048576, DIM=2, HID=64, E=4, hard top-1.
// Output (float32): [ out (N*2) | router_logits (N*4) ]
//
// R6: layer-2 GEMM on tf32 HMMA, SINGLE product (mma.m16n8k8 tf32):
// tf32's 11-bit mantissa + 64-term averaging in layers 2/3 keeps the
// propagated output error ~1e-4 (<< 1e-3 threshold) while cutting the MMA
// count 192->128 per warp and removing the bf16 split entirely (1 cvt per h).
// prep is folded into router blocks 0-3; router does 2 tokens/thread.

typedef unsigned long long U64;

static constexpr int N_MAX = 1 << 20;
static constexpr int TILE  = 128;

__device__ int d_cnt[4];
__device__ int d_perm[4 * N_MAX];
// tf32 B fragments: [e][kstep(8)][nt(8)][lane(32)] uint2
__device__ uint2 d_w2f[4 * 8 * 8 * 32];

// ---------------- helpers ----------------
__device__ __forceinline__ U64 fma2(U64 a, U64 b, U64 c) {
    U64 d;
    asm("fma.rn.f32x2 %0, %1, %2, %3;" : "=l"(d) : "l"(a), "l"(b), "l"(c));
    return d;
}
__device__ __forceinline__ U64 pack2(float lo, float hi) {
    U64 r;
    asm("mov.b64 %0, {%1, %2};" : "=l"(r) : "f"(lo), "f"(hi));
    return r;
}
__device__ __forceinline__ void unpack2(U64 v, float& lo, float& hi) {
    asm("mov.b64 {%0, %1}, %2;" : "=f"(lo), "=f"(hi) : "l"(v));
}
__device__ __forceinline__ uint32_t tf32_of(float f) {
    uint32_t r;
    asm("cvt.rna.tf32.f32 %0, %1;" : "=r"(r) : "f"(f));
    return r;
}
__device__ __forceinline__ void mma_tf32(float c[4], const uint32_t a[4],
                                         uint32_t b0, uint32_t b1) {
    asm volatile(
        "mma.sync.aligned.m16n8k8.row.col.f32.tf32.tf32.f32 "
        "{%0,%1,%2,%3}, {%4,%5,%6,%7}, {%8,%9}, {%0,%1,%2,%3};"
        : "+f"(c[0]), "+f"(c[1]), "+f"(c[2]), "+f"(c[3])
        : "r"(a[0]), "r"(a[1]), "r"(a[2]), "r"(a[3]), "r"(b0), "r"(b1));
}

// ---------------- Kernel 1: router (2 tok/thread) + fused w2 prep ---------
__global__ __launch_bounds__(256)
void router_kernel(const float* __restrict__ x,
                   const float* __restrict__ rW,
                   const float* __restrict__ rb,
                   const float* __restrict__ w2,
                   float* __restrict__ out, int n)
{
    __shared__ int scnt[4], gbase[4];
    const int tid = threadIdx.x;
    if (tid < 4) scnt[tid] = 0;

    // fused prep: blocks 0-3 build expert e = blockIdx.x's tf32 B fragments
    if (blockIdx.x < 4) {
        const int e = blockIdx.x;
        #pragma unroll
        for (int t = tid; t < 2048; t += 256) {
            const int ks = t >> 8, nt = (t >> 5) & 7, lane = t & 31;
            const int k0 = ks * 8 + (lane & 3);
            const int nn = nt * 8 + (lane >> 2);
            const float v0 = w2[e * 4096 + k0 * 64 + nn];
            const float v1 = w2[e * 4096 + (k0 + 4) * 64 + nn];
            d_w2f[((e * 8 + ks) * 8 + nt) * 32 + lane] =
                make_uint2(tf32_of(v0), tf32_of(v1));
        }
    }
    __syncthreads();

    const float rw0 = rW[0], rw1 = rW[1], rw2 = rW[2], rw3 = rW[3];
    const float rw4 = rW[4], rw5 = rW[5], rw6 = rW[6], rw7 = rW[7];
    const float rb0 = rb[0], rb1 = rb[1], rb2 = rb[2], rb3 = rb[3];

    const int base = blockIdx.x * 512;                // 2 tokens per thread
    const float4 xq = ((const float4*)x)[base / 2 + tid];
    const unsigned lane = tid & 31;

    int bests[2], wbs[2];
    #pragma unroll
    for (int s = 0; s < 2; s++) {
        const int i = base + 2 * tid + s;
        const float x0 = s ? xq.z : xq.x;
        const float x1 = s ? xq.w : xq.y;
        const float l0 = fmaf(x0, rw0, fmaf(x1, rw4, rb0));
        const float l1 = fmaf(x0, rw1, fmaf(x1, rw5, rb1));
        const float l2 = fmaf(x0, rw2, fmaf(x1, rw6, rb2));
        const float l3 = fmaf(x0, rw3, fmaf(x1, rw7, rb3));
        int best = 0; float bl = l0;
        if (l1 > bl) { bl = l1; best = 1; }
        if (l2 > bl) { bl = l2; best = 2; }
        if (l3 > bl) { bl = l3; best = 3; }
        ((float4*)(out + 2 * (size_t)n))[i] = make_float4(l0, l1, l2, l3);

        unsigned m[4];
        #pragma unroll
        for (int e = 0; e < 4; e++)
            m[e] = __ballot_sync(0xffffffffu, best == e);
        const unsigned mym = m[best];
        const int rank   = __popc(mym & ((1u << lane) - 1));
        const int leader = __ffs(mym) - 1;
        int wb = 0;
        if ((int)lane == leader) wb = atomicAdd(&scnt[best], __popc(mym));
        wb = __shfl_sync(0xffffffffu, wb, leader);
        bests[s] = best;
        wbs[s] = wb + rank;
    }
    __syncthreads();
    if (tid < 4) gbase[tid] = atomicAdd(&d_cnt[tid], scnt[tid]);
    __syncthreads();

    #pragma unroll
    for (int s = 0; s < 2; s++)
        d_perm[bests[s] * N_MAX + gbase[bests[s]] + wbs[s]] = base + 2 * tid + s;
}

// ---------------- Kernel 2: expert tile (tf32 HMMA) -----------------------
__global__ __launch_bounds__(128, 4)
void expert_kernel(const float* __restrict__ x,
                   const float* __restrict__ w1,
                   const float* __restrict__ b1,
                   const float* __restrict__ b2,
                   const float* __restrict__ w3,
                   const float* __restrict__ b3,
                   float* __restrict__ out)
{
    __shared__ uint2  sBf[2048];          // [kstep][nt][lane]
    __shared__ float2 sX[128];
    __shared__ float  sW1[128];           // [d][i]
    __shared__ float  sB1[64], sB2[64];
    __shared__ __align__(8) float sW3[128];
    __shared__ float  sB3[2];
    __shared__ int    sIdx[128];

    // --- map blockIdx -> (expert, tile) ---
    const int c0 = d_cnt[0], c1 = d_cnt[1], c2 = d_cnt[2], c3 = d_cnt[3];
    const int t0 = (c0 + TILE - 1) / TILE, t1 = (c1 + TILE - 1) / TILE;
    const int t2 = (c2 + TILE - 1) / TILE, t3 = (c3 + TILE - 1) / TILE;
    int b = blockIdx.x, e, lo, cnt;
    if (b < t0)              { e = 0; lo = b; cnt = c0; }
    else if ((b -= t0) < t1) { e = 1; lo = b; cnt = c1; }
    else if ((b -= t1) < t2) { e = 2; lo = b; cnt = c2; }
    else if ((b -= t2) < t3) { e = 3; lo = b; cnt = c3; }
    else return;

    const int tid = threadIdx.x;
    const int tstart = lo * TILE;
    int mvalid = cnt - tstart;
    if (mvalid > TILE) mvalid = TILE;

    // --- stage ---
    {
        const uint4* gB = ((const uint4*)d_w2f) + e * 1024;
        uint4* sB4 = (uint4*)sBf;
        #pragma unroll
        for (int t = tid; t < 1024; t += 128) sB4[t] = gB[t];
        sW1[tid] = w1[e * 128 + tid];
        sW3[tid] = w3[e * 128 + tid];
        if (tid < 64) { sB1[tid] = b1[e * 64 + tid]; sB2[tid] = b2[e * 64 + tid]; }
        if (tid < 2)  sB3[tid] = b3[e * 2 + tid];
        const int token = d_perm[e * N_MAX + tstart + (tid < mvalid ? tid : 0)];
        sIdx[tid] = token;
        sX[tid] = ((const float2*)x)[token];
    }
    __syncthreads();

    const int lane = tid & 31, wid = tid >> 5;
    const int qr = lane >> 2;             // row-in-8
    const int kb = lane & 3;              // k-in-4
    const int rbase = wid * 32 + qr;

    float xr[4], yr[4];                   // rows rbase + {0,8,16,24}
    #pragma unroll
    for (int r = 0; r < 4; r++) {
        const float2 v = sX[rbase + r * 8];
        xr[r] = v.x; yr[r] = v.y;
    }

    float acc[2][8][4];
    #pragma unroll
    for (int mt = 0; mt < 2; mt++)
        #pragma unroll
        for (int nt = 0; nt < 8; nt++)
            #pragma unroll
            for (int q = 0; q < 4; q++) acc[mt][nt][q] = 0.f;

    #pragma unroll
    for (int ks = 0; ks < 8; ks++) {
        const int k = ks * 8 + kb;        // this thread's k and k+4
        const float wa0 = sW1[k],      wa4 = sW1[k + 4];
        const float wb0 = sW1[64 + k], wb4 = sW1[64 + k + 4];
        const float bb0 = sB1[k],      bb4 = sB1[k + 4];

        uint32_t A[2][4];
        #pragma unroll
        for (int r = 0; r < 4; r++) {     // r = 2*mt + p (p: +0 / +8 row)
            const float h0 = fmaxf(fmaf(xr[r], wa0, fmaf(yr[r], wb0, bb0)), 0.f);
            const float h4 = fmaxf(fmaf(xr[r], wa4, fmaf(yr[r], wb4, bb4)), 0.f);
            const int mt = r >> 1, p = r & 1;
            A[mt][p]     = tf32_of(h0);
            A[mt][p + 2] = tf32_of(h4);
        }

        #pragma unroll
        for (int nt = 0; nt < 8; nt++) {
            const uint2 B = sBf[(ks * 8 + nt) * 32 + lane];
            mma_tf32(acc[0][nt], A[0], B.x, B.y);
            mma_tf32(acc[1][nt], A[1], B.x, B.y);
        }
    }

    // --- epilogue: b2 + relu + fused layer 3, reduce over 4 n-lanes ---
    const U64* w3p = (const U64*)sW3;
    const int jb = kb * 2;
    #pragma unroll
    for (int mt = 0; mt < 2; mt++) {
        U64 po0 = 0ull, po1 = 0ull;
        #pragma unroll
        for (int nt = 0; nt < 8; nt++) {
            const int j0 = nt * 8 + jb, j1 = j0 + 1;
            float c;
            c = fmaxf(acc[mt][nt][0] + sB2[j0], 0.f);
            po0 = fma2(pack2(c, c), w3p[j0], po0);
            c = fmaxf(acc[mt][nt][1] + sB2[j1], 0.f);
            po0 = fma2(pack2(c, c), w3p[j1], po0);
            c = fmaxf(acc[mt][nt][2] + sB2[j0], 0.f);
            po1 = fma2(pack2(c, c), w3p[j0], po1);
            c = fmaxf(acc[mt][nt][3] + sB2[j1], 0.f);
            po1 = fma2(pack2(c, c), w3p[j1], po1);
        }
        float a0, a1, c0v, c1v;
        unpack2(po0, a0, a1);
        unpack2(po1, c0v, c1v);
        #pragma unroll
        for (int s = 1; s < 4; s <<= 1) {
            a0  += __shfl_xor_sync(0xffffffffu, a0,  s);
            a1  += __shfl_xor_sync(0xffffffffu, a1,  s);
            c0v += __shfl_xor_sync(0xffffffffu, c0v, s);
            c1v += __shfl_xor_sync(0xffffffffu, c1v, s);
        }
        if (kb == 0) {
            const int r0 = wid * 32 + mt * 16 + qr;
            if (r0 < mvalid)
                ((float2*)out)[sIdx[r0]] = make_float2(a0 + sB3[0], a1 + sB3[1]);
            const int r1 = r0 + 8;
            if (r1 < mvalid)
                ((float2*)out)[sIdx[r1]] = make_float2(c0v + sB3[0], c1v + sB3[1]);
        }
    }
}

extern "C" void kernel_launch(void* const* d_in, const int* in_sizes, int n_in,
                              void* d_out, int out_size)
{
    const float* x  = (const float*)d_in[0];
    const float* rW = (const float*)d_in[1];
    const float* rb = (const float*)d_in[2];
    const float* w1 = (const float*)d_in[3];
    const float* b1 = (const float*)d_in[4];
    const float* w2 = (const float*)d_in[5];
    const float* b2 = (const float*)d_in[6];
    const float* w3 = (const float*)d_in[7];
    const float* b3 = (const float*)d_in[8];
    float* out = (float*)d_out;

    const int n_tok = in_sizes[0] / 2;

    void* cnt_addr = nullptr;
    cudaGetSymbolAddress(&cnt_addr, d_cnt);
    cudaMemsetAsync(cnt_addr, 0, 4 * sizeof(int));

    router_kernel<<<n_tok / 512, 256>>>(x, rW, rb, w2, out, n_tok);

    const int max_tiles = n_tok / TILE + 3;   // per-expert ceil slack
    expert_kernel<<<max_tiles, 128>>>(x, w1, b1, b2, w3, b3, out);
}